// round 15
// baseline (speedup 1.0000x reference)
#include <cuda_runtime.h>
#include <cuda_fp16.h>
#include <cstdint>
#include <cstddef>

#define NT   131072
#define KDIM 2048
#define HID  256
#define NE   64

// Split scaling: keep fp16 residuals out of subnormal range.
#define WSCALE 1024.0f
#define XSCALE 16.0f
#define UNSCALE (1.0f / 16384.0f)

// ---------------- scratch (__device__ globals; allocation-rule compliant) ---
__device__ float g_h[(size_t)NT * HID];
__device__ float g_probsum[NE];
__device__ unsigned int g_count[NE];
__device__ __half g_w1t_hi[(size_t)HID * KDIM];   // (W1*1024)^T split hi [n][k]
__device__ __half g_w1t_lo[(size_t)HID * KDIM];

// ---------------- helpers ---------------------------------------------------
__device__ __forceinline__ uint32_t smem_u32(const void* p) {
    uint32_t a;
    asm("{ .reg .u64 t; cvta.to.shared.u64 t, %1; cvt.u32.u64 %0, t; }" : "=r"(a) : "l"(p));
    return a;
}

#define CP16(dst, src) asm volatile("cp.async.cg.shared.global [%0], [%1], 16;" :: "r"(dst), "l"(src) : "memory")
#define CP_COMMIT()    asm volatile("cp.async.commit_group;" ::: "memory")
#define CP_WAIT0()     asm volatile("cp.async.wait_group 0;" ::: "memory")

#define LDSM4(r0, r1, r2, r3, a) \
    asm volatile("ldmatrix.sync.aligned.m8n8.x4.shared.b16 {%0,%1,%2,%3}, [%4];" \
        : "=r"(r0), "=r"(r1), "=r"(r2), "=r"(r3) : "r"(a))

#define MMA16816(d, a, b0, b1) \
    asm volatile("mma.sync.aligned.m16n8k16.row.col.f32.f16.f16.f32 " \
        "{%0,%1,%2,%3},{%4,%5,%6,%7},{%8,%9},{%0,%1,%2,%3};" \
        : "+f"((d)[0]), "+f"((d)[1]), "+f"((d)[2]), "+f"((d)[3]) \
        : "r"((a)[0]), "r"((a)[1]), "r"((a)[2]), "r"((a)[3]), "r"(b0), "r"(b1))

// 16B-group swizzle within 128B rows (8 groups): conflict-free for st.v4 +
// ldmatrix — any 8 consecutive rows map the same logical group to 8 distinct
// 16B columns (full 32-bank coverage).
__device__ __forceinline__ uint32_t swzB(uint32_t row, uint32_t grp) {
    return row * 128u + ((grp ^ (row & 7u)) << 4);
}

// ---------------------------------------------------------------------------
// GEMM1: h = relu(x @ W1 + b1) via mma.sync fp16 3-pass split, fp32 accum.
// K-chunk 64 (was 32): half the barriers/loop overhead, longer MMA runs
// between sync-aligned bubbles. Stage 64KB, double-buffered (128KB smem).
// ---------------------------------------------------------------------------
__global__ __launch_bounds__(256) void gemm1_mma(const float* __restrict__ x,
                                                 const float* __restrict__ b1)
{
    extern __shared__ __align__(1024) char smem[];
    const uint32_t sb = smem_u32(smem);
    const int tid  = threadIdx.x;
    const int wid  = tid >> 5, lane = tid & 31;
    const int warpM = wid >> 2;      // 0..1 -> m offset *64
    const int warpN = wid & 3;       // 0..3 -> n offset *32
    const int mbase = (blockIdx.x >> 1) * 128;
    const int nbase = (blockIdx.x & 1) * 128;

    // stage layout (64KB/stage): Ahi 16K | Alo 16K | Bhi 16K | Blo 16K
    const uint32_t STG = 65536;
    const uint32_t AHI = sb, ALO = sb + 16384, BHI = sb + 32768, BLO = sb + 49152;

    // -------- B loader (cp.async): W1^T hi/lo [128 n][64 k] --------
    auto cpB = [&](int c, int s) {
        const int k0 = c * 64;
        const uint32_t bh = BHI + s * STG, bl = BLO + s * STG;
#pragma unroll
        for (int i = 0; i < 4; i++) {
            int cell = tid + (i << 8);          // 1024 cells: 128 rows x 8 grps
            int row = cell >> 3, grp = cell & 7;
            uint32_t o = swzB(row, grp);
            CP16(bh + o, g_w1t_hi + (size_t)(nbase + row) * KDIM + k0 + grp * 8);
            CP16(bl + o, g_w1t_lo + (size_t)(nbase + row) * KDIM + k0 + grp * 8);
        }
    };

    // -------- A loader: x fp32 -> regs (8 float4) --------
    auto ldX = [&](int c, float4* xr) {
        const int k0 = c * 64;
#pragma unroll
        for (int i = 0; i < 4; i++) {
            int cell = tid + (i << 8);          // 1024 cells: 128 rows x 8 grps
            int row = cell >> 3, grp = cell & 7;
            const float4* src = reinterpret_cast<const float4*>(
                x + (size_t)(mbase + row) * KDIM + k0 + grp * 8);
            xr[i * 2 + 0] = src[0];
            xr[i * 2 + 1] = src[1];
        }
    };

    // -------- A split (scaled by 16) + smem store --------
    auto cvtSt = [&](int s, const float4* xr) {
        const uint32_t ah = AHI + s * STG, al = ALO + s * STG;
#pragma unroll
        for (int i = 0; i < 4; i++) {
            int cell = tid + (i << 8);
            int row = cell >> 3, grp = cell & 7;
            float4 v0 = xr[i * 2 + 0], v1 = xr[i * 2 + 1];
            v0.x *= XSCALE; v0.y *= XSCALE; v0.z *= XSCALE; v0.w *= XSCALE;
            v1.x *= XSCALE; v1.y *= XSCALE; v1.z *= XSCALE; v1.w *= XSCALE;
            __half2 h0 = __floats2half2_rn(v0.x, v0.y);
            __half2 h1 = __floats2half2_rn(v0.z, v0.w);
            __half2 h2 = __floats2half2_rn(v1.x, v1.y);
            __half2 h3 = __floats2half2_rn(v1.z, v1.w);
            float2 f0 = __half22float2(h0), f1 = __half22float2(h1);
            float2 f2 = __half22float2(h2), f3 = __half22float2(h3);
            __half2 l0 = __floats2half2_rn(v0.x - f0.x, v0.y - f0.y);
            __half2 l1 = __floats2half2_rn(v0.z - f1.x, v0.w - f1.y);
            __half2 l2 = __floats2half2_rn(v1.x - f2.x, v1.y - f2.y);
            __half2 l3 = __floats2half2_rn(v1.z - f3.x, v1.w - f3.y);
            uint32_t o = swzB(row, grp);
            asm volatile("st.shared.v4.b32 [%0], {%1,%2,%3,%4};"
                :: "r"(ah + o), "r"(*(uint32_t*)&h0), "r"(*(uint32_t*)&h1),
                   "r"(*(uint32_t*)&h2), "r"(*(uint32_t*)&h3) : "memory");
            asm volatile("st.shared.v4.b32 [%0], {%1,%2,%3,%4};"
                :: "r"(al + o), "r"(*(uint32_t*)&l0), "r"(*(uint32_t*)&l1),
                   "r"(*(uint32_t*)&l2), "r"(*(uint32_t*)&l3) : "memory");
        }
    };

    float d[4][4][4];
#pragma unroll
    for (int i = 0; i < 4; i++)
#pragma unroll
        for (int j = 0; j < 4; j++)
#pragma unroll
            for (int r = 0; r < 4; r++) d[i][j][r] = 0.f;

    // -------- compute one stage: 4 k16 steps, 3 split passes each --------
    auto compute = [&](int s) {
        const uint32_t ah = AHI + s * STG, al = ALO + s * STG;
        const uint32_t bh = BHI + s * STG, bl = BLO + s * STG;
#pragma unroll
        for (int k16 = 0; k16 < 4; k16++) {
            const uint32_t grp = k16 * 2 + (lane >> 4);     // 0..7
            uint32_t Ah[4][4], Al[4][4];
            const uint32_t arow = warpM * 64 + (lane & 15);
#pragma unroll
            for (int mf = 0; mf < 4; mf++) {
                uint32_t o = swzB(arow + mf * 16, grp);
                LDSM4(Ah[mf][0], Ah[mf][1], Ah[mf][2], Ah[mf][3], ah + o);
                LDSM4(Al[mf][0], Al[mf][1], Al[mf][2], Al[mf][3], al + o);
            }
            uint32_t Bh[4][2], Bl[4][2];
            const uint32_t brow = warpN * 32 + (lane & 15);
#pragma unroll
            for (int nb = 0; nb < 2; nb++) {
                uint32_t o = swzB(brow + nb * 16, grp);
                uint32_t r0, r1, r2, r3;
                LDSM4(r0, r1, r2, r3, bh + o);
                Bh[nb * 2][0] = r0; Bh[nb * 2][1] = r2;
                Bh[nb * 2 + 1][0] = r1; Bh[nb * 2 + 1][1] = r3;
                LDSM4(r0, r1, r2, r3, bl + o);
                Bl[nb * 2][0] = r0; Bl[nb * 2][1] = r2;
                Bl[nb * 2 + 1][0] = r1; Bl[nb * 2 + 1][1] = r3;
            }
#pragma unroll
            for (int mf = 0; mf < 4; mf++)
#pragma unroll
                for (int nf = 0; nf < 4; nf++) {
                    MMA16816(d[mf][nf], Ah[mf], Bh[nf][0], Bh[nf][1]);
                    MMA16816(d[mf][nf], Ah[mf], Bl[nf][0], Bl[nf][1]);
                    MMA16816(d[mf][nf], Al[mf], Bh[nf][0], Bh[nf][1]);
                }
        }
    };

    // -------- pipeline --------
    constexpr int NC = KDIM / 64;   // 32 chunks
    float4 xr[8];

    cpB(0, 0); CP_COMMIT();
    ldX(0, xr);
    cvtSt(0, xr);
    CP_WAIT0();
    __syncthreads();

    for (int c = 0; c < NC; c++) {
        const int s = c & 1;
        const bool more = (c + 1 < NC);
        if (more) { cpB(c + 1, s ^ 1); CP_COMMIT(); ldX(c + 1, xr); }
        compute(s);
        if (more) { cvtSt(s ^ 1, xr); CP_WAIT0(); }
        __syncthreads();
    }

    // -------- epilogue: unscale + bias + relu -> g_h --------
#pragma unroll
    for (int mf = 0; mf < 4; mf++) {
        const int r0 = warpM * 64 + mf * 16 + (lane >> 2);
#pragma unroll
        for (int nf = 0; nf < 4; nf++) {
            const int c = nbase + warpN * 32 + nf * 8 + (lane & 3) * 2;
            const float bx = b1[c], by = b1[c + 1];
            float2 v0 = make_float2(fmaxf(fmaf(d[mf][nf][0], UNSCALE, bx), 0.f),
                                    fmaxf(fmaf(d[mf][nf][1], UNSCALE, by), 0.f));
            float2 v1 = make_float2(fmaxf(fmaf(d[mf][nf][2], UNSCALE, bx), 0.f),
                                    fmaxf(fmaf(d[mf][nf][3], UNSCALE, by), 0.f));
            size_t base = (size_t)(mbase + r0) * HID + c;
            *reinterpret_cast<float2*>(&g_h[base]) = v0;
            *reinterpret_cast<float2*>(&g_h[base + (size_t)8 * HID]) = v1;
        }
    }
}

// ---------------------------------------------------------------------------
// Prep: W1^T scaled split + zero accumulators (merged, one launch).
// ---------------------------------------------------------------------------
__global__ void prep_w(const float* __restrict__ W1) {
    int i = blockIdx.x * 256 + threadIdx.x;
    if (i < KDIM * HID) {
        int k = i >> 8, n = i & 255;      // W1[k][n], n contiguous
        float w = W1[i] * WSCALE;
        __half h = __float2half_rn(w);
        g_w1t_hi[(size_t)n * KDIM + k] = h;
        g_w1t_lo[(size_t)n * KDIM + k] = __float2half_rn(w - __half2float(h));
    }
    if (i < NE) { g_probsum[i] = 0.f; g_count[i] = 0u; }
}

// ---------------------------------------------------------------------------
// FUSED GEMM2 + ROUTER (exact fp32 GEMM — logit error budget requires it).
// BM=64 tokens/CTA, 3 CTAs/SM; router tails overlap other CTAs' GEMMs.
// ---------------------------------------------------------------------------
#define FMA2(d, a, b) asm("fma.rn.f32x2 %0, %1, %2, %0;" : "+l"(d) : "l"(a), "l"(b))
__device__ __forceinline__ unsigned long long pack2(float f) {
    unsigned long long r; unsigned int u = __float_as_uint(f);
    asm("mov.b64 %0, {%1, %1};" : "=l"(r) : "r"(u));
    return r;
}
__device__ __forceinline__ float2 unpack2(unsigned long long v) {
    unsigned int lo, hi;
    asm("mov.b64 {%0, %1}, %2;" : "=r"(lo), "=r"(hi) : "l"(v));
    return make_float2(__uint_as_float(lo), __uint_as_float(hi));
}

#define LSTR 68   // smem logits row stride (floats): 16B-aligned, conflict-free

__global__ __launch_bounds__(256, 3) void gemm2_router(
    const float* __restrict__ B, const float* __restrict__ bias,
    float* __restrict__ out)
{
    constexpr int BM = 64, BN = 64, BK = 16, TM = 4, TN = 4;
    __shared__ float As[BK][BM + 4];
    __shared__ float Bs[BK][BN];
    __shared__ float slog[BM * LSTR];

    const float* A = g_h;
    constexpr int K = HID, N = NE;

    const int tid = threadIdx.x;
    const int tx  = tid & 15;
    const int ty  = tid >> 4;
    const long rowBase = (long)blockIdx.x * BM;

    const int ar = tid >> 2, ac = (tid & 3) << 2;
    const int br = tid >> 4, bc = (tid & 15) << 2;

    unsigned long long acc[TM / 2][TN];
#pragma unroll
    for (int i = 0; i < TM / 2; i++)
#pragma unroll
        for (int j = 0; j < TN; j++) acc[i][j] = 0ull;

    const float* Aptr = A + (rowBase + ar) * (long)K + ac;
    const float* Bptr = B + (long)br * N + bc;

    for (int k0 = 0; k0 < K; k0 += BK) {
        float4 a0 = *reinterpret_cast<const float4*>(Aptr + k0);
        float4 bv = *reinterpret_cast<const float4*>(Bptr + (long)k0 * N);

        As[ac + 0][ar] = a0.x; As[ac + 1][ar] = a0.y;
        As[ac + 2][ar] = a0.z; As[ac + 3][ar] = a0.w;
        *reinterpret_cast<float4*>(&Bs[br][bc]) = bv;
        __syncthreads();

#pragma unroll
        for (int kk = 0; kk < BK; kk++) {
            const ulonglong2* ap = reinterpret_cast<const ulonglong2*>(&As[kk][ty * TM]);
            ulonglong2 av = ap[0];
            unsigned long long am[2] = { av.x, av.y };
            float4 bq = *reinterpret_cast<const float4*>(&Bs[kk][tx * TN]);
            unsigned long long bp[4] = { pack2(bq.x), pack2(bq.y), pack2(bq.z), pack2(bq.w) };
#pragma unroll
            for (int i = 0; i < 2; i++)
#pragma unroll
                for (int j = 0; j < 4; j++)
                    FMA2(acc[i][j], am[i], bp[j]);
        }
        __syncthreads();
    }

    float bsv[TN];
#pragma unroll
    for (int j = 0; j < TN; j++) bsv[j] = bias[tx * TN + j];

#pragma unroll
    for (int i = 0; i < TM / 2; i++) {
        float2 r0 = unpack2(acc[i][0]), r1 = unpack2(acc[i][1]);
        float2 r2 = unpack2(acc[i][2]), r3 = unpack2(acc[i][3]);
        float4 o0 = make_float4(r0.x + bsv[0], r1.x + bsv[1], r2.x + bsv[2], r3.x + bsv[3]);
        float4 o1 = make_float4(r0.y + bsv[0], r1.y + bsv[1], r2.y + bsv[2], r3.y + bsv[3]);
        int row0 = ty * TM + i * 2;
        *reinterpret_cast<float4*>(&slog[row0 * LSTR + tx * TN]) = o0;
        *reinterpret_cast<float4*>(&slog[(row0 + 1) * LSTR + tx * TN]) = o1;
    }
    __syncthreads();

    // ---- router on the smem tile: warp w handles tokens w*8..w*8+7 ----
    const int lane = threadIdx.x & 31;
    const int wid  = threadIdx.x >> 5;

    float psum0 = 0.f, psum1 = 0.f;
    unsigned int cnt0 = 0, cnt1 = 0;

    for (int tl = wid * 8; tl < wid * 8 + 8; tl++) {
        const float* lp = slog + tl * LSTR;
        float l0 = lp[lane];
        float l1 = lp[lane + 32];

        float v1, v2; int i1, i2;
        if (l1 > l0) { v1 = l1; i1 = lane + 32; v2 = l0; i2 = lane; }
        else         { v1 = l0; i1 = lane;      v2 = l1; i2 = lane + 32; }

#pragma unroll
        for (int off = 16; off > 0; off >>= 1) {
            float qv1 = __shfl_xor_sync(0xffffffffu, v1, off);
            int   qi1 = __shfl_xor_sync(0xffffffffu, i1, off);
            float qv2 = __shfl_xor_sync(0xffffffffu, v2, off);
            int   qi2 = __shfl_xor_sync(0xffffffffu, i2, off);
            if (qv1 > v1 || (qv1 == v1 && qi1 < i1)) {
                if (v1 > qv2 || (v1 == qv2 && i1 < qi2)) { v2 = v1; i2 = i1; }
                else                                     { v2 = qv2; i2 = qi2; }
                v1 = qv1; i1 = qi1;
            } else {
                if (qv1 > v2 || (qv1 == v2 && qi1 < i2)) { v2 = qv1; i2 = qi1; }
            }
        }

        float e0 = expf(l0 - v1);
        float e1 = expf(l1 - v1);
        float s = e0 + e1;
#pragma unroll
        for (int off = 16; off > 0; off >>= 1)
            s += __shfl_xor_sync(0xffffffffu, s, off);
        float inv = 1.0f / s;
        psum0 += e0 * inv;
        psum1 += e1 * inv;

        cnt0 += (unsigned)(i1 == lane)      + (unsigned)(i2 == lane);
        cnt1 += (unsigned)(i1 == lane + 32) + (unsigned)(i2 == lane + 32);

        if (lane == 0) {
            size_t t = (size_t)rowBase + tl;
            float eg = expf(v2 - v1);
            float gs = 1.0f + eg;
            out[2 * t]             = (float)i1;
            out[2 * t + 1]         = (float)i2;
            out[2 * (size_t)NT + 2 * t]     = 1.0f / gs;
            out[2 * (size_t)NT + 2 * t + 1] = eg / gs;
        }
    }

    atomicAdd(&g_probsum[lane], psum0);
    atomicAdd(&g_probsum[lane + 32], psum1);
    atomicAdd(&g_count[lane], cnt0);
    atomicAdd(&g_count[lane + 32], cnt1);
}

__global__ void finalize_kernel(float* __restrict__ out) {
    int lane = threadIdx.x;
    float term = 0.f;
    for (int e = lane; e < NE; e += 32)
        term += ((float)g_count[e] / (float)NT) * (g_probsum[e] / (float)NT);
#pragma unroll
    for (int off = 16; off > 0; off >>= 1)
        term += __shfl_xor_sync(0xffffffffu, term, off);
    if (lane == 0) out[(size_t)4 * NT] = (float)NE * term;
}

// ---------------------------------------------------------------------------
extern "C" void kernel_launch(void* const* d_in, const int* in_sizes, int n_in,
                              void* d_out, int out_size) {
    (void)in_sizes; (void)n_in; (void)out_size;
    const float* x  = (const float*)d_in[0];
    const float* W1 = (const float*)d_in[1];
    const float* b1 = (const float*)d_in[2];
    const float* W2 = (const float*)d_in[3];
    const float* b2 = (const float*)d_in[4];
    float* out = (float*)d_out;

    static bool smem_set = false;
    if (!smem_set) {
        cudaFuncSetAttribute(gemm1_mma, cudaFuncAttributeMaxDynamicSharedMemorySize, 131072);
        smem_set = true;
    }

    prep_w<<<(KDIM * HID) / 256, 256>>>(W1);

    gemm1_mma<<<(NT / 128) * 2, 256, 131072>>>(x, b1);

    gemm2_router<<<NT / 64, 256>>>(W2, b2, out);

    finalize_kernel<<<1, 32>>>(out);
}

// round 16
// speedup vs baseline: 1.0268x; 1.0268x over previous
#include <cuda_runtime.h>
#include <cuda_fp16.h>
#include <cstdint>
#include <cstddef>

#define NT   131072
#define KDIM 2048
#define HID  256
#define NE   64

// Split scaling: keep fp16 residuals out of subnormal range.
#define WSCALE 1024.0f
#define XSCALE 16.0f
#define UNSCALE (1.0f / 16384.0f)

// ---------------- scratch (__device__ globals; allocation-rule compliant) ---
__device__ float g_h[(size_t)NT * HID];
__device__ float g_probsum[NE];
__device__ unsigned int g_count[NE];
__device__ __half g_w1t_hi[(size_t)HID * KDIM];   // (W1*1024)^T split hi [n][k]
__device__ __half g_w1t_lo[(size_t)HID * KDIM];

// ---------------- helpers ---------------------------------------------------
__device__ __forceinline__ uint32_t smem_u32(const void* p) {
    uint32_t a;
    asm("{ .reg .u64 t; cvta.to.shared.u64 t, %1; cvt.u32.u64 %0, t; }" : "=r"(a) : "l"(p));
    return a;
}

#define CP16(dst, src) asm volatile("cp.async.cg.shared.global [%0], [%1], 16;" :: "r"(dst), "l"(src) : "memory")
#define CP_COMMIT()    asm volatile("cp.async.commit_group;" ::: "memory")
#define CP_WAIT0()     asm volatile("cp.async.wait_group 0;" ::: "memory")

#define LDSM4(r0, r1, r2, r3, a) \
    asm volatile("ldmatrix.sync.aligned.m8n8.x4.shared.b16 {%0,%1,%2,%3}, [%4];" \
        : "=r"(r0), "=r"(r1), "=r"(r2), "=r"(r3) : "r"(a))

#define MMA16816(d, a, b0, b1) \
    asm volatile("mma.sync.aligned.m16n8k16.row.col.f32.f16.f16.f32 " \
        "{%0,%1,%2,%3},{%4,%5,%6,%7},{%8,%9},{%0,%1,%2,%3};" \
        : "+f"((d)[0]), "+f"((d)[1]), "+f"((d)[2]), "+f"((d)[3]) \
        : "r"((a)[0]), "r"((a)[1]), "r"((a)[2]), "r"((a)[3]), "r"(b0), "r"(b1))

// 16B-group swizzle within 64B rows: conflict-free for st.v4 + ldmatrix
__device__ __forceinline__ uint32_t swz(uint32_t row, uint32_t grp) {
    return row * 64u + ((grp ^ (row & 3u)) << 4);
}

// ---------------------------------------------------------------------------
// GEMM1: h = relu(x @ W1 + b1) via mma.sync fp16 3-pass split, fp32 accum.
// K-chunk 32, 256 threads, 64KB smem — the validated optimum (R11).
// ---------------------------------------------------------------------------
__global__ __launch_bounds__(256) void gemm1_mma(const float* __restrict__ x,
                                                 const float* __restrict__ b1)
{
    extern __shared__ __align__(1024) char smem[];
    const uint32_t sb = smem_u32(smem);
    const int tid  = threadIdx.x;
    const int wid  = tid >> 5, lane = tid & 31;
    const int warpM = wid >> 2;      // 0..1 -> m offset *64
    const int warpN = wid & 3;       // 0..3 -> n offset *32
    const int mbase = (blockIdx.x >> 1) * 128;
    const int nbase = (blockIdx.x & 1) * 128;

    // stage layout (per stage 32KB): Ahi 8K | Alo 8K | Bhi 8K | Blo 8K
    const uint32_t STG = 32768;
    const uint32_t AHI = sb, ALO = sb + 8192, BHI = sb + 16384, BLO = sb + 24576;

    auto cpB = [&](int c, int s) {
        const int k0 = c * 32;
        const uint32_t bh = BHI + s * STG, bl = BLO + s * STG;
#pragma unroll
        for (int i = 0; i < 2; i++) {
            int cell = tid + (i << 8);          // 512 cells
            int row = cell >> 2, grp = cell & 3;
            uint32_t o = swz(row, grp);
            CP16(bh + o, g_w1t_hi + (size_t)(nbase + row) * KDIM + k0 + grp * 8);
            CP16(bl + o, g_w1t_lo + (size_t)(nbase + row) * KDIM + k0 + grp * 8);
        }
    };

    auto ldX = [&](int c, float4* xr) {
        const int k0 = c * 32;
#pragma unroll
        for (int i = 0; i < 2; i++) {
            int cell = tid + (i << 8);
            int row = cell >> 2, grp = cell & 3;
            const float4* src = reinterpret_cast<const float4*>(
                x + (size_t)(mbase + row) * KDIM + k0 + grp * 8);
            xr[i * 2 + 0] = src[0];
            xr[i * 2 + 1] = src[1];
        }
    };

    auto cvtSt = [&](int s, const float4* xr) {
        const uint32_t ah = AHI + s * STG, al = ALO + s * STG;
#pragma unroll
        for (int i = 0; i < 2; i++) {
            int cell = tid + (i << 8);
            int row = cell >> 2, grp = cell & 3;
            float4 v0 = xr[i * 2 + 0], v1 = xr[i * 2 + 1];
            v0.x *= XSCALE; v0.y *= XSCALE; v0.z *= XSCALE; v0.w *= XSCALE;
            v1.x *= XSCALE; v1.y *= XSCALE; v1.z *= XSCALE; v1.w *= XSCALE;
            __half2 h0 = __floats2half2_rn(v0.x, v0.y);
            __half2 h1 = __floats2half2_rn(v0.z, v0.w);
            __half2 h2 = __floats2half2_rn(v1.x, v1.y);
            __half2 h3 = __floats2half2_rn(v1.z, v1.w);
            float2 f0 = __half22float2(h0), f1 = __half22float2(h1);
            float2 f2 = __half22float2(h2), f3 = __half22float2(h3);
            __half2 l0 = __floats2half2_rn(v0.x - f0.x, v0.y - f0.y);
            __half2 l1 = __floats2half2_rn(v0.z - f1.x, v0.w - f1.y);
            __half2 l2 = __floats2half2_rn(v1.x - f2.x, v1.y - f2.y);
            __half2 l3 = __floats2half2_rn(v1.z - f3.x, v1.w - f3.y);
            uint32_t o = swz(row, grp);
            asm volatile("st.shared.v4.b32 [%0], {%1,%2,%3,%4};"
                :: "r"(ah + o), "r"(*(uint32_t*)&h0), "r"(*(uint32_t*)&h1),
                   "r"(*(uint32_t*)&h2), "r"(*(uint32_t*)&h3) : "memory");
            asm volatile("st.shared.v4.b32 [%0], {%1,%2,%3,%4};"
                :: "r"(al + o), "r"(*(uint32_t*)&l0), "r"(*(uint32_t*)&l1),
                   "r"(*(uint32_t*)&l2), "r"(*(uint32_t*)&l3) : "memory");
        }
    };

    float d[4][4][4];
#pragma unroll
    for (int i = 0; i < 4; i++)
#pragma unroll
        for (int j = 0; j < 4; j++)
#pragma unroll
            for (int r = 0; r < 4; r++) d[i][j][r] = 0.f;

    auto compute = [&](int s) {
        const uint32_t ah = AHI + s * STG, al = ALO + s * STG;
        const uint32_t bh = BHI + s * STG, bl = BLO + s * STG;
#pragma unroll
        for (int k16 = 0; k16 < 2; k16++) {
            const uint32_t grp = k16 * 2 + (lane >> 4);
            uint32_t Ah[4][4], Al[4][4];
            const uint32_t arow = warpM * 64 + (lane & 15);
#pragma unroll
            for (int mf = 0; mf < 4; mf++) {
                uint32_t o = swz(arow + mf * 16, grp);
                LDSM4(Ah[mf][0], Ah[mf][1], Ah[mf][2], Ah[mf][3], ah + o);
                LDSM4(Al[mf][0], Al[mf][1], Al[mf][2], Al[mf][3], al + o);
            }
            uint32_t Bh[4][2], Bl[4][2];
            const uint32_t brow = warpN * 32 + (lane & 15);
#pragma unroll
            for (int nb = 0; nb < 2; nb++) {
                uint32_t o = swz(brow + nb * 16, grp);
                uint32_t r0, r1, r2, r3;
                LDSM4(r0, r1, r2, r3, bh + o);
                Bh[nb * 2][0] = r0; Bh[nb * 2][1] = r2;
                Bh[nb * 2 + 1][0] = r1; Bh[nb * 2 + 1][1] = r3;
                LDSM4(r0, r1, r2, r3, bl + o);
                Bl[nb * 2][0] = r0; Bl[nb * 2][1] = r2;
                Bl[nb * 2 + 1][0] = r1; Bl[nb * 2 + 1][1] = r3;
            }
#pragma unroll
            for (int mf = 0; mf < 4; mf++)
#pragma unroll
                for (int nf = 0; nf < 4; nf++) {
                    MMA16816(d[mf][nf], Ah[mf], Bh[nf][0], Bh[nf][1]);
                    MMA16816(d[mf][nf], Ah[mf], Bl[nf][0], Bl[nf][1]);
                    MMA16816(d[mf][nf], Al[mf], Bh[nf][0], Bh[nf][1]);
                }
        }
    };

    constexpr int NC = KDIM / 32;   // 64 chunks
    float4 xr[4];

    cpB(0, 0); CP_COMMIT();
    ldX(0, xr);
    cvtSt(0, xr);
    CP_WAIT0();
    __syncthreads();

    for (int c = 0; c < NC; c++) {
        const int s = c & 1;
        const bool more = (c + 1 < NC);
        if (more) { cpB(c + 1, s ^ 1); CP_COMMIT(); ldX(c + 1, xr); }
        compute(s);
        if (more) { cvtSt(s ^ 1, xr); CP_WAIT0(); }
        __syncthreads();
    }

#pragma unroll
    for (int mf = 0; mf < 4; mf++) {
        const int r0 = warpM * 64 + mf * 16 + (lane >> 2);
#pragma unroll
        for (int nf = 0; nf < 4; nf++) {
            const int c = nbase + warpN * 32 + nf * 8 + (lane & 3) * 2;
            const float bx = b1[c], by = b1[c + 1];
            float2 v0 = make_float2(fmaxf(fmaf(d[mf][nf][0], UNSCALE, bx), 0.f),
                                    fmaxf(fmaf(d[mf][nf][1], UNSCALE, by), 0.f));
            float2 v1 = make_float2(fmaxf(fmaf(d[mf][nf][2], UNSCALE, bx), 0.f),
                                    fmaxf(fmaf(d[mf][nf][3], UNSCALE, by), 0.f));
            size_t base = (size_t)(mbase + r0) * HID + c;
            *reinterpret_cast<float2*>(&g_h[base]) = v0;
            *reinterpret_cast<float2*>(&g_h[base + (size_t)8 * HID]) = v1;
        }
    }
}

// ---------------------------------------------------------------------------
// Prep: W1^T scaled split + zero accumulators (merged, one launch).
// ---------------------------------------------------------------------------
__global__ void prep_w(const float* __restrict__ W1) {
    int i = blockIdx.x * 256 + threadIdx.x;
    if (i < KDIM * HID) {
        int k = i >> 8, n = i & 255;      // W1[k][n], n contiguous
        float w = W1[i] * WSCALE;
        __half h = __float2half_rn(w);
        g_w1t_hi[(size_t)n * KDIM + k] = h;
        g_w1t_lo[(size_t)n * KDIM + k] = __float2half_rn(w - __half2float(h));
    }
    if (i < NE) { g_probsum[i] = 0.f; g_count[i] = 0u; }
}

// ---------------------------------------------------------------------------
// FUSED GEMM2 + ROUTER (exact fp32 GEMM — logit error budget requires it).
// BM=128 tokens/CTA (R12 configuration, best single measured run).
// ---------------------------------------------------------------------------
#define FMA2(d, a, b) asm("fma.rn.f32x2 %0, %1, %2, %0;" : "+l"(d) : "l"(a), "l"(b))
__device__ __forceinline__ unsigned long long pack2(float f) {
    unsigned long long r; unsigned int u = __float_as_uint(f);
    asm("mov.b64 %0, {%1, %1};" : "=l"(r) : "r"(u));
    return r;
}
__device__ __forceinline__ float2 unpack2(unsigned long long v) {
    unsigned int lo, hi;
    asm("mov.b64 {%0, %1}, %2;" : "=r"(lo), "=r"(hi) : "l"(v));
    return make_float2(__uint_as_float(lo), __uint_as_float(hi));
}

#define LSTR 68   // smem logits row stride (floats): 16B-aligned, conflict-free

__global__ __launch_bounds__(256, 2) void gemm2_router(
    const float* __restrict__ B, const float* __restrict__ bias,
    float* __restrict__ out)
{
    constexpr int BM = 128, BN = 64, BK = 16, TM = 8, TN = 4;
    __shared__ float As[BK][BM + 4];
    __shared__ float Bs[BK][BN];
    __shared__ float slog[BM * LSTR];

    const float* A = g_h;
    constexpr int K = HID, N = NE;

    const int tid = threadIdx.x;
    const int tx  = tid & 15;
    const int ty  = tid >> 4;
    const long rowBase = (long)blockIdx.x * BM;

    const int ar = tid >> 2, ac = (tid & 3) << 2;
    const int br = tid >> 4, bc = (tid & 15) << 2;

    unsigned long long acc[TM / 2][TN];
#pragma unroll
    for (int i = 0; i < TM / 2; i++)
#pragma unroll
        for (int j = 0; j < TN; j++) acc[i][j] = 0ull;

    const float* Aptr0 = A + (rowBase + ar) * (long)K + ac;
    const float* Aptr1 = Aptr0 + (long)64 * K;
    const float* Bptr  = B + (long)br * N + bc;

    for (int k0 = 0; k0 < K; k0 += BK) {
        float4 a0 = *reinterpret_cast<const float4*>(Aptr0 + k0);
        float4 a1 = *reinterpret_cast<const float4*>(Aptr1 + k0);
        float4 bv = *reinterpret_cast<const float4*>(Bptr + (long)k0 * N);

        As[ac + 0][ar] = a0.x; As[ac + 1][ar] = a0.y;
        As[ac + 2][ar] = a0.z; As[ac + 3][ar] = a0.w;
        As[ac + 0][ar + 64] = a1.x; As[ac + 1][ar + 64] = a1.y;
        As[ac + 2][ar + 64] = a1.z; As[ac + 3][ar + 64] = a1.w;
        *reinterpret_cast<float4*>(&Bs[br][bc]) = bv;
        __syncthreads();

#pragma unroll
        for (int kk = 0; kk < BK; kk++) {
            const ulonglong2* ap = reinterpret_cast<const ulonglong2*>(&As[kk][ty * TM]);
            ulonglong2 av0 = ap[0], av1 = ap[1];
            unsigned long long am[4] = { av0.x, av0.y, av1.x, av1.y };
            float4 bq = *reinterpret_cast<const float4*>(&Bs[kk][tx * TN]);
            unsigned long long bp[4] = { pack2(bq.x), pack2(bq.y), pack2(bq.z), pack2(bq.w) };
#pragma unroll
            for (int i = 0; i < 4; i++)
#pragma unroll
                for (int j = 0; j < 4; j++)
                    FMA2(acc[i][j], am[i], bp[j]);
        }
        __syncthreads();
    }

    // epilogue: bias, store logits tile into smem
    float bsv[TN];
#pragma unroll
    for (int j = 0; j < TN; j++) bsv[j] = bias[tx * TN + j];

#pragma unroll
    for (int i = 0; i < TM / 2; i++) {
        float2 r0 = unpack2(acc[i][0]), r1 = unpack2(acc[i][1]);
        float2 r2 = unpack2(acc[i][2]), r3 = unpack2(acc[i][3]);
        float4 o0 = make_float4(r0.x + bsv[0], r1.x + bsv[1], r2.x + bsv[2], r3.x + bsv[3]);
        float4 o1 = make_float4(r0.y + bsv[0], r1.y + bsv[1], r2.y + bsv[2], r3.y + bsv[3]);
        int row0 = ty * TM + i * 2;
        *reinterpret_cast<float4*>(&slog[row0 * LSTR + tx * TN]) = o0;
        *reinterpret_cast<float4*>(&slog[(row0 + 1) * LSTR + tx * TN]) = o1;
    }
    __syncthreads();

    // ---- router on the smem tile: warp w handles tokens w*16..w*16+15 ----
    const int lane = threadIdx.x & 31;
    const int wid  = threadIdx.x >> 5;

    float psum0 = 0.f, psum1 = 0.f;
    unsigned int cnt0 = 0, cnt1 = 0;

    for (int tl = wid * 16; tl < wid * 16 + 16; tl++) {
        const float* lp = slog + tl * LSTR;
        float l0 = lp[lane];
        float l1 = lp[lane + 32];

        float v1, v2; int i1, i2;
        if (l1 > l0) { v1 = l1; i1 = lane + 32; v2 = l0; i2 = lane; }
        else         { v1 = l0; i1 = lane;      v2 = l1; i2 = lane + 32; }

#pragma unroll
        for (int off = 16; off > 0; off >>= 1) {
            float qv1 = __shfl_xor_sync(0xffffffffu, v1, off);
            int   qi1 = __shfl_xor_sync(0xffffffffu, i1, off);
            float qv2 = __shfl_xor_sync(0xffffffffu, v2, off);
            int   qi2 = __shfl_xor_sync(0xffffffffu, i2, off);
            if (qv1 > v1 || (qv1 == v1 && qi1 < i1)) {
                if (v1 > qv2 || (v1 == qv2 && i1 < qi2)) { v2 = v1; i2 = i1; }
                else                                     { v2 = qv2; i2 = qi2; }
                v1 = qv1; i1 = qi1;
            } else {
                if (qv1 > v2 || (qv1 == v2 && qi1 < i2)) { v2 = qv1; i2 = qi1; }
            }
        }

        float e0 = expf(l0 - v1);
        float e1 = expf(l1 - v1);
        float s = e0 + e1;
#pragma unroll
        for (int off = 16; off > 0; off >>= 1)
            s += __shfl_xor_sync(0xffffffffu, s, off);
        float inv = 1.0f / s;
        psum0 += e0 * inv;
        psum1 += e1 * inv;

        cnt0 += (unsigned)(i1 == lane)      + (unsigned)(i2 == lane);
        cnt1 += (unsigned)(i1 == lane + 32) + (unsigned)(i2 == lane + 32);

        if (lane == 0) {
            size_t t = (size_t)rowBase + tl;
            float eg = expf(v2 - v1);
            float gs = 1.0f + eg;
            out[2 * t]             = (float)i1;
            out[2 * t + 1]         = (float)i2;
            out[2 * (size_t)NT + 2 * t]     = 1.0f / gs;
            out[2 * (size_t)NT + 2 * t + 1] = eg / gs;
        }
    }

    atomicAdd(&g_probsum[lane], psum0);
    atomicAdd(&g_probsum[lane + 32], psum1);
    atomicAdd(&g_count[lane], cnt0);
    atomicAdd(&g_count[lane + 32], cnt1);
}

__global__ void finalize_kernel(float* __restrict__ out) {
    int lane = threadIdx.x;
    float term = 0.f;
    for (int e = lane; e < NE; e += 32)
        term += ((float)g_count[e] / (float)NT) * (g_probsum[e] / (float)NT);
#pragma unroll
    for (int off = 16; off > 0; off >>= 1)
        term += __shfl_xor_sync(0xffffffffu, term, off);
    if (lane == 0) out[(size_t)4 * NT] = (float)NE * term;
}

// ---------------------------------------------------------------------------
extern "C" void kernel_launch(void* const* d_in, const int* in_sizes, int n_in,
                              void* d_out, int out_size) {
    (void)in_sizes; (void)n_in; (void)out_size;
    const float* x  = (const float*)d_in[0];
    const float* W1 = (const float*)d_in[1];
    const float* b1 = (const float*)d_in[2];
    const float* W2 = (const float*)d_in[3];
    const float* b2 = (const float*)d_in[4];
    float* out = (float*)d_out;

    static bool smem_set = false;
    if (!smem_set) {
        cudaFuncSetAttribute(gemm1_mma, cudaFuncAttributeMaxDynamicSharedMemorySize, 65536);
        smem_set = true;
    }

    prep_w<<<(KDIM * HID) / 256, 256>>>(W1);

    gemm1_mma<<<(NT / 128) * 2, 256, 65536>>>(x, b1);

    gemm2_router<<<NT / 128, 256>>>(W2, b2, out);

    finalize_kernel<<<1, 32>>>(out);
}